// round 15
// baseline (speedup 1.0000x reference)
#include <cuda_runtime.h>
#include <math.h>

// S4D real SSM, v9: ONE kernel. v4's proven fused lookback body (39.8us) +
//  - constants (a, cb, dc) computed inline per block (no precompute launch)
//  - monotonic epoch flags: every block bumps its flag twice per replay
//    (aggregate, then prefix), so no reset kernel is needed; the replay base
//    is recovered from the block's own aggregate atomicAdd return value.

#define LEN 4096
#define CH  512
#define S   64
#define NC  32
#define LC  128
#define CS  (CH*S)
#define DTF (1.0f/4096.0f)

#define NPK 4              // f32x2 pairs per lane (8 states)
#define SPL 8              // states per lane
#define CPW 4              // channels per warp
#define CPB 32             // channels per block
#define NG  (CH/CPB)       // 16 channel groups

typedef unsigned long long ull;

__device__ float g_v[NC*CS];     // chunk aggregates
__device__ float g_p[NC*CS];     // inclusive chunk prefixes
__device__ int   g_flag[NC*NG];  // monotonic epoch counters (+2 per replay)

// ---- packed f32x2 helpers (Blackwell FFMA2, PTX-only) ---------------------
__device__ __forceinline__ ull pack2(float x, float y) {
    ull r; asm("mov.b64 %0, {%1, %2};" : "=l"(r) : "f"(x), "f"(y)); return r;
}
__device__ __forceinline__ ull fma2(ull a, ull b, ull c) {
    ull d; asm("fma.rn.f32x2 %0, %1, %2, %3;" : "=l"(d) : "l"(a), "l"(b), "l"(c)); return d;
}
__device__ __forceinline__ ull mul2(ull a, ull b) {
    ull d; asm("mul.rn.f32x2 %0, %1, %2;" : "=l"(d) : "l"(a), "l"(b)); return d;
}
__device__ __forceinline__ float hsum2(ull v) {
    float lo, hi; asm("mov.b64 {%0, %1}, %2;" : "=f"(lo), "=f"(hi) : "l"(v));
    return lo + hi;
}
__device__ __forceinline__ int ld_rlx(const int* p) {
    int v; asm volatile("ld.relaxed.gpu.global.b32 %0, [%1];" : "=r"(v) : "l"(p) : "memory");
    return v;
}

// ---------------------------------------------------------------- fused
__global__ __launch_bounds__(256, 4)
void fused_k(const float* __restrict__ x,
             const float* __restrict__ lognegA,
             const float* __restrict__ B,
             const float* __restrict__ C,
             float* __restrict__ y)
{
    __shared__ ull sx[LC][CPB];          // packed {x,x} tile, 32 KB
    __shared__ int s_base;
    const int k     = blockIdx.x;        // chunk
    const int gb    = blockIdx.y;        // channel group
    const int cbase = gb * CPB;
    const int tid   = threadIdx.x;
    const int w     = tid >> 5;
    const int lane  = tid & 31;
    const int g     = lane >> 3;         // channel within warp
    const int q     = lane & 7;          // lane within 8-lane channel team
    const int l0    = k * LC;

    // ---- tile load: float4 from gmem, duplicated into packed ull smem
    #pragma unroll 4
    for (int i = tid; i < LC * CPB / 4; i += 256) {
        int lr = i >> 3, c4 = (i & 7) << 2;
        float4 v4 = *reinterpret_cast<const float4*>(x + (l0 + lr) * CH + cbase + c4);
        sx[lr][c4 + 0] = pack2(v4.x, v4.x);
        sx[lr][c4 + 1] = pack2(v4.y, v4.y);
        sx[lr][c4 + 2] = pack2(v4.z, v4.z);
        sx[lr][c4 + 3] = pack2(v4.w, v4.w);
    }

    const int c     = cbase + w * CPW + g;
    const int sbase = c * S + q * SPL;
    const int chl   = w * CPW + g;

    // ---- inline per-state constants (overlaps the tile DRAM load)
    // a  = exp(A*dt); dc = a^LC; cb = C*B*DTF*(1 + ad*(1/2 + ad/6))
    //   [expm1(ad)/A = DTF*expm1(ad)/ad; |ad|<=0.016 -> Taylor err ~2e-7]
    float av[SPL], cbv[SPL], dcv[SPL];
    #pragma unroll
    for (int t = 0; t < SPL; t++) {
        float ad = -__expf(lognegA[sbase + t]) * DTF;
        av [t] = __expf(ad);
        dcv[t] = __expf(ad * (float)LC);
        cbv[t] = C[sbase + t] * B[sbase + t] * DTF
                 * (1.0f + ad * (0.5f + ad * (1.0f / 6.0f)));
    }
    ull a[NPK], cb[NPK], dc[NPK];
    #pragma unroll
    for (int t = 0; t < NPK; t++) {
        a [t] = pack2(av [2 * t], av [2 * t + 1]);
        cb[t] = pack2(cbv[2 * t], cbv[2 * t + 1]);
        dc[t] = pack2(dcv[2 * t], dcv[2 * t + 1]);
    }
    __syncthreads();

    // ---- phase 1: chunk aggregate (zero initial state)
    ull v[NPK] = {0ull, 0ull, 0ull, 0ull};
    #pragma unroll 8
    for (int l = 0; l < LC; l++) {
        ull xx = sx[l][chl];
        #pragma unroll
        for (int t = 0; t < NPK; t++) v[t] = fma2(a[t], v[t], xx);
    }

    // ---- publish aggregate; epoch base from own atomicAdd return
    {
        ull* vP = reinterpret_cast<ull*>(g_v + k * CS + sbase);
        #pragma unroll
        for (int t = 0; t < NPK; t++) vP[t] = v[t];
        __threadfence();
        __syncthreads();
        if (tid == 0) s_base = atomicAdd(&g_flag[k * NG + gb], 1);
        __syncthreads();
    }
    const int base = s_base;   // flag[j] - base: >=1 aggregate, >=2 prefix

    // ---- phase 2: decoupled lookback (typically terminates in 1 hop)
    ull h[NPK] = {0ull, 0ull, 0ull, 0ull};
    if (k > 0) {
        const ull one = pack2(1.f, 1.f);
        ull dpow[NPK]  = {one, one, one, one};
        ull carry[NPK] = {0ull, 0ull, 0ull, 0ull};
        int j = k - 1;
        while (1) {
            int st = 0;
            if (lane == 0) {
                st = ld_rlx(&g_flag[j * NG + gb]) - base;
                while (st < 1) { __nanosleep(40); st = ld_rlx(&g_flag[j * NG + gb]) - base; }
            }
            st = __shfl_sync(0xffffffffu, st, 0);
            __threadfence();                  // acquire for g_v/g_p reads
            if (st >= 2) {                    // predecessor prefix: terminate
                const ull* pP = reinterpret_cast<const ull*>(g_p + j * CS + sbase);
                #pragma unroll
                for (int t = 0; t < NPK; t++) carry[t] = fma2(dpow[t], __ldcg(pP + t), carry[t]);
                break;
            } else {                          // aggregate only: accumulate, step back
                const ull* jv = reinterpret_cast<const ull*>(g_v + j * CS + sbase);
                #pragma unroll
                for (int t = 0; t < NPK; t++) carry[t] = fma2(dpow[t], __ldcg(jv + t), carry[t]);
                #pragma unroll
                for (int t = 0; t < NPK; t++) dpow[t] = mul2(dpow[t], dc[t]);
                if (--j < 0) break;           // summed all aggregates: done
            }
        }
        #pragma unroll
        for (int t = 0; t < NPK; t++) h[t] = carry[t];
    }

    // ---- publish inclusive prefix P_k = dc*h0 + v (every block: keeps
    //      the flag advance uniform at +2 per replay)
    {
        ull* pP = reinterpret_cast<ull*>(g_p + k * CS + sbase);
        #pragma unroll
        for (int t = 0; t < NPK; t++) pP[t] = fma2(dc[t], h[t], v[t]);
        __threadfence();
        __syncthreads();
        if (tid == 0) atomicAdd(&g_flag[k * NG + gb], 1);
    }

    // ---- phase 3: output recurrence from h0
    #pragma unroll 2
    for (int r = 0; r < LC / 8; r++) {
        float p[8];
        #pragma unroll
        for (int j = 0; j < 8; j++) {
            ull xx = sx[r * 8 + j][chl];
            #pragma unroll
            for (int t = 0; t < NPK; t++) h[t] = fma2(a[t], h[t], xx);
            ull acc = mul2(cb[0], h[0]);
            #pragma unroll
            for (int t = 1; t < NPK; t++) acc = fma2(cb[t], h[t], acc);
            p[j] = hsum2(acc);
        }
        // 3-stage register-halving butterfly over the 8-lane team:
        // afterwards lane q holds the finished output for step r*8+q
        #pragma unroll
        for (int d = 4; d >= 1; d >>= 1) {
            #pragma unroll
            for (int m = 0; m < d; m++) {
                bool  hi   = (q & d) != 0;
                float send = hi ? p[m] : p[m + d];
                float got  = __shfl_xor_sync(0xffffffffu, send, d);
                p[m] = (hi ? p[m + d] : p[m]) + got;
            }
        }
        y[(l0 + r * 8 + q) * CH + c] = p[0];
    }
}

// ---------------------------------------------------------------- launch
extern "C" void kernel_launch(void* const* d_in, const int* in_sizes, int n_in,
                              void* d_out, int out_size)
{
    const float* x       = (const float*)d_in[0];
    const float* lognegA = (const float*)d_in[1];
    const float* B       = (const float*)d_in[2];
    const float* C       = (const float*)d_in[3];
    float*       y       = (float*)d_out;

    dim3 grid(NC, NG);
    fused_k<<<grid, 256>>>(x, lognegA, B, C, y);
}

// round 16
// speedup vs baseline: 1.3729x; 1.3729x over previous
#include <cuda_runtime.h>
#include <math.h>

// S4D real SSM, v10: R7's proven 4-kernel split (52.0us) minus the precompute
// launch. Kernel-boundary sync only — no atomics, no flags, no spinning.
//   passA: inline a=exp(A*dt) per thread (overlaps tile load); k==0 blocks
//          also materialize g_a/g_cb/g_dc. Writes per-chunk aggregates g_v.
//   scan : serial prefix over NC chunks per state -> g_h0.
//   passC: EXACT R7 kernel (measured 19.0us): recurrence + 8-lane butterfly.

#define LEN   4096
#define CH    512
#define S     64
#define NC    64            // chunks over L
#define LC    64            // chunk length
#define CS    (CH*S)        // 32768 states
#define DTF   (1.0f/4096.0f)

#define SPL   8             // states per lane
#define NPK   4             // packed f32x2 pairs per lane
#define CPW   4             // channels per warp
#define CPB   32            // channels per block

typedef unsigned long long ull;

__device__ float g_a [CS];      // exp(A*dt)
__device__ float g_cb[CS];      // C * Bd
__device__ float g_dc[CS];      // exp(A*dt*LC)
__device__ float g_v [NC*CS];   // per-chunk contribution (h0 = 0)
__device__ float g_h0[NC*CS];   // per-chunk initial state

// ---- packed f32x2 helpers (Blackwell FFMA2 path, PTX-only) ----------------
__device__ __forceinline__ ull pack2(float x, float y) {
    ull r; asm("mov.b64 %0, {%1, %2};" : "=l"(r) : "f"(x), "f"(y)); return r;
}
__device__ __forceinline__ ull fma2(ull a, ull b, ull c) {
    ull d; asm("fma.rn.f32x2 %0, %1, %2, %3;" : "=l"(d) : "l"(a), "l"(b), "l"(c)); return d;
}
__device__ __forceinline__ ull mul2(ull a, ull b) {
    ull d; asm("mul.rn.f32x2 %0, %1, %2;" : "=l"(d) : "l"(a), "l"(b)); return d;
}
__device__ __forceinline__ float hsum2(ull v) {
    float lo, hi; asm("mov.b64 {%0, %1}, %2;" : "=f"(lo), "=f"(hi) : "l"(v));
    return lo + hi;
}

// ---------------------------------------------------------------- pass A
// grid (NC, CH/CPB), block 256 (8 warps). Lane owns 8 states (4 pairs) of one
// channel. Constants computed inline; k==0 blocks materialize them for later.
__global__ __launch_bounds__(256, 6)
void passA_k(const float* __restrict__ x,
             const float* __restrict__ lognegA,
             const float* __restrict__ B,
             const float* __restrict__ C)
{
    __shared__ float sx[LC][CPB];
    const int chunk = blockIdx.x;
    const int cbase = blockIdx.y * CPB;
    const int tid   = threadIdx.x;
    const int w     = tid >> 5;
    const int lane  = tid & 31;
    const int g     = lane >> 3;      // channel within warp (0..3)
    const int q     = lane & 7;       // lane within channel group (0..7)
    const int l0    = chunk * LC;

    #pragma unroll
    for (int i = tid; i < LC * CPB; i += 256) {
        int lr = i >> 5, cc = i & (CPB - 1);
        sx[lr][cc] = x[(l0 + lr) * CH + cbase + cc];
    }

    const int c     = cbase + w * CPW + g;
    const int sbase = c * S + q * SPL;
    const int chl   = w * CPW + g;

    // inline per-state decay (overlaps the tile DRAM load)
    float av[SPL];
    #pragma unroll
    for (int t = 0; t < SPL; t++) {
        float ad = -__expf(lognegA[sbase + t]) * DTF;
        av[t] = __expf(ad);
    }
    ull a[NPK];
    #pragma unroll
    for (int t = 0; t < NPK; t++) a[t] = pack2(av[2 * t], av[2 * t + 1]);

    if (chunk == 0) {   // materialize constants for scan_k / passC_k
        #pragma unroll
        for (int t = 0; t < SPL; t++) {
            float A  = -__expf(lognegA[sbase + t]);
            float ad = A * DTF;
            float Bd = expm1f(ad) / A * B[sbase + t];   // cancellation-safe
            g_a [sbase + t] = av[t];
            g_cb[sbase + t] = C[sbase + t] * Bd;
            g_dc[sbase + t] = __expf(ad * (float)LC);
        }
    }
    __syncthreads();

    ull h[NPK] = {0ull, 0ull, 0ull, 0ull};
    #pragma unroll
    for (int l = 0; l < LC; l++) {
        float xv = sx[l][chl];
        ull   xx = pack2(xv, xv);
        #pragma unroll
        for (int t = 0; t < NPK; t++) h[t] = fma2(a[t], h[t], xx);
    }

    ull* vP = reinterpret_cast<ull*>(g_v + chunk * CS + sbase);
    #pragma unroll
    for (int t = 0; t < NPK; t++) vP[t] = h[t];
}

// ---------------------------------------------------------------- chunk scan
__global__ void scan_k()
{
    int i = blockIdx.x * blockDim.x + threadIdx.x;
    if (i >= CS) return;
    const float d = g_dc[i];
    float h = 0.f;
    #pragma unroll 8
    for (int k = 0; k < NC; k++) {
        g_h0[k * CS + i] = h;
        h = fmaf(d, h, g_v[k * CS + i]);
    }
}

// ---------------------------------------------------------------- pass C
// EXACT R7 kernel (measured 19.0us): starts from g_h0, emits y. Outputs
// buffered 8 steps, 3-stage register-halving butterfly within each 8-lane
// team (7 warp-shfl serve 4 channels x 8 steps), direct 16B-aligned stores.
__global__ __launch_bounds__(256, 5)
void passC_k(const float* __restrict__ x, float* __restrict__ y)
{
    __shared__ float sx[LC][CPB];
    const int chunk = blockIdx.x;
    const int cbase = blockIdx.y * CPB;
    const int tid   = threadIdx.x;
    const int w     = tid >> 5;
    const int lane  = tid & 31;
    const int g     = lane >> 3;
    const int q     = lane & 7;
    const int l0    = chunk * LC;

    #pragma unroll
    for (int i = tid; i < LC * CPB; i += 256) {
        int lr = i >> 5, cc = i & (CPB - 1);
        sx[lr][cc] = x[(l0 + lr) * CH + cbase + cc];
    }
    __syncthreads();

    const int c     = cbase + w * CPW + g;
    const int sbase = c * S + q * SPL;
    const int chl   = w * CPW + g;

    ull a[NPK], cb[NPK], h[NPK];
    const ull* aP  = reinterpret_cast<const ull*>(g_a  + sbase);
    const ull* cbP = reinterpret_cast<const ull*>(g_cb + sbase);
    const ull* hP  = reinterpret_cast<const ull*>(g_h0 + chunk * CS + sbase);
    #pragma unroll
    for (int k = 0; k < NPK; k++) { a[k] = aP[k]; cb[k] = cbP[k]; h[k] = hP[k]; }

    #pragma unroll
    for (int r = 0; r < LC / 8; r++) {
        float p[8];
        #pragma unroll
        for (int j = 0; j < 8; j++) {
            float xv = sx[r * 8 + j][chl];
            ull   xx = pack2(xv, xv);
            #pragma unroll
            for (int k = 0; k < NPK; k++) h[k] = fma2(a[k], h[k], xx);
            ull acc = mul2(cb[0], h[0]);
            #pragma unroll
            for (int k = 1; k < NPK; k++) acc = fma2(cb[k], h[k], acc);
            p[j] = hsum2(acc);
        }
        // 3-stage register-halving butterfly over the 8-lane team:
        // afterwards lane q holds the finished output for step r*8+q
        #pragma unroll
        for (int d = 4; d >= 1; d >>= 1) {
            #pragma unroll
            for (int m = 0; m < d; m++) {
                bool  hi   = (q & d) != 0;
                float send = hi ? p[m] : p[m + d];
                float got  = __shfl_xor_sync(0xffffffffu, send, d);
                p[m] = (hi ? p[m + d] : p[m]) + got;
            }
        }
        y[(l0 + r * 8 + q) * CH + c] = p[0];
    }
}

// ---------------------------------------------------------------- launch
extern "C" void kernel_launch(void* const* d_in, const int* in_sizes, int n_in,
                              void* d_out, int out_size)
{
    const float* x       = (const float*)d_in[0];
    const float* lognegA = (const float*)d_in[1];
    const float* B       = (const float*)d_in[2];
    const float* C       = (const float*)d_in[3];
    float*       y       = (float*)d_out;

    dim3 grid(NC, CH / CPB);
    passA_k<<<grid, 256>>>(x, lognegA, B, C);
    scan_k<<<(CS + 255) / 256, 256>>>();
    passC_k<<<grid, 256>>>(x, y);
}